// round 2
// baseline (speedup 1.0000x reference)
#include <cuda_runtime.h>
#include <math.h>

#define TT 2048
#define BB 64
#define IN1 256
#define HH 512
#define GG 2048   // 4*HH
#define NCTA 128

// ---------------- scratch (static device globals; allocation-free) ----------
__device__ float g_xg[(size_t)TT * BB * GG];   // 1 GB: xg for current layer
__device__ float g_h [(size_t)TT * BB * HH];   // 256 MB: h history (h1 then h2)
__device__ unsigned g_bar;                     // grid barrier arrival counter
__device__ unsigned g_done;                    // end-of-kernel reset counter

// ---------------- GEMM: C[M,N] = A[M,K] * W[N,K]^T + b1[N] + b2[N] ----------
__global__ void __launch_bounds__(256) gemm_xg(
    const float* __restrict__ A, const float* __restrict__ W,
    const float* __restrict__ b1, const float* __restrict__ b2,
    float* __restrict__ C, int M, int N, int K)
{
    __shared__ float As[16][132];
    __shared__ float Bs[16][132];
    const int bm = blockIdx.y * 128;
    const int bn = blockIdx.x * 128;
    const int tid = threadIdx.x;
    const int tx = tid & 15;
    const int ty = tid >> 4;

    float acc[8][8];
#pragma unroll
    for (int i = 0; i < 8; i++)
#pragma unroll
        for (int j = 0; j < 8; j++) acc[i][j] = 0.f;

    for (int k0 = 0; k0 < K; k0 += 16) {
#pragma unroll
        for (int i = 0; i < 2; i++) {
            int li  = tid + i * 256;        // 0..511 (float4 index)
            int row = li >> 2;              // 0..127
            int kc  = (li & 3) << 2;        // 0,4,8,12
            float4 va = *(const float4*)(A + (size_t)(bm + row) * K + k0 + kc);
            As[kc+0][row] = va.x; As[kc+1][row] = va.y;
            As[kc+2][row] = va.z; As[kc+3][row] = va.w;
            float4 vb = *(const float4*)(W + (size_t)(bn + row) * K + k0 + kc);
            Bs[kc+0][row] = vb.x; Bs[kc+1][row] = vb.y;
            Bs[kc+2][row] = vb.z; Bs[kc+3][row] = vb.w;
        }
        __syncthreads();
#pragma unroll
        for (int k = 0; k < 16; k++) {
            float a[8], b[8];
            *(float4*)&a[0] = *(float4*)&As[k][ty * 8];
            *(float4*)&a[4] = *(float4*)&As[k][ty * 8 + 4];
            *(float4*)&b[0] = *(float4*)&Bs[k][tx * 8];
            *(float4*)&b[4] = *(float4*)&Bs[k][tx * 8 + 4];
#pragma unroll
            for (int i = 0; i < 8; i++)
#pragma unroll
                for (int j = 0; j < 8; j++) acc[i][j] += a[i] * b[j];
        }
        __syncthreads();
    }

#pragma unroll
    for (int i = 0; i < 8; i++) {
        int row = bm + ty * 8 + i;
#pragma unroll
        for (int j = 0; j < 8; j++) {
            int col = bn + tx * 8 + j;
            C[(size_t)row * N + col] = acc[i][j] + b1[col] + b2[col];
        }
    }
}

// ---------------- persistent LSTM layer (all T steps in one launch) ---------
// 128 CTAs; CTA owns 4 hidden units u0..u0+3 => 16 gate rows r=q*4+v
// (global gate row = q*512 + u0 + v; q = 0:i 1:f 2:g 3:o, PyTorch order).
// W_hh slice resident in SMEM for the whole layer; cell state in registers.
// Cross-CTA sync per step via monotonic global barrier (all CTAs co-resident:
// 1 CTA/SM at 169 KB smem, 128 CTAs <= 148 SMs).
#define SW 516                 // padded SMEM row (conflict-free, float4-aligned)
#define SMEM_LSTM ((size_t)((16 + 64) * SW + 16 * 66) * sizeof(float))

__global__ void __launch_bounds__(256) lstm_layer(
    const float* __restrict__ Whh,   // (2048, 512)
    float* __restrict__ h_all,       // (T, B, H): read t-1, write t
    const float* __restrict__ xg)    // (T, B, 4H) precomputed x-gates (+biases)
{
    extern __shared__ float sm[];
    float* Ws = sm;                      // [16][SW]
    float* Hs = sm + 16 * SW;            // [64][SW]
    float* Gs = sm + (16 + 64) * SW;     // [16][66]

    const int tid = threadIdx.x;
    const int u0  = blockIdx.x * 4;
    const int w = tid >> 5;
    const int l = tid & 31;

    // Load W slice once: 16 rows x 512 (float4, coalesced)
#pragma unroll
    for (int i = 0; i < 8; i++) {
        int li = tid + i * 256;           // 0..2047 f4-index
        int r  = li >> 7;                 // 0..15
        int c4 = li & 127;
        int grow = ((r >> 2) << 9) + u0 + (r & 3);
        float4 v = *(const float4*)(Whh + (size_t)grow * HH + (c4 << 2));
        *(float4*)&Ws[r * SW + (c4 << 2)] = v;
    }

    // Cell state in a register: thread (v = tid>>6, b = tid&63) owns c[u0+v][b]
    const int pv = tid >> 6;
    const int pb = tid & 63;
    float creg = 0.f;

    // Precomputed indices for the gate-staging phase
    const int r0 = 2 * w, r1 = 2 * w + 1;
    const int gr0 = ((r0 >> 2) << 9) + u0 + (r0 & 3);
    const int gr1 = ((r1 >> 2) << 9) + u0 + (r1 & 3);

    for (int t = 0; t < TT; t++) {
        if (t > 0) {
            // Wait until all CTAs finished writing h(t-1)
            if (tid == 0) {
                unsigned target = (unsigned)NCTA * (unsigned)t;
                while (*(volatile unsigned*)&g_bar < target) __nanosleep(32);
            }
            __syncthreads();
            __threadfence();   // acquire: order h reads after the spin

            const float* hprev = h_all + (size_t)(t - 1) * BB * HH;
#pragma unroll
            for (int i = 0; i < 32; i++) {
                int li = tid + i * 256;       // 0..8191 f4-index
                int b  = li >> 7;             // 0..63
                int c4 = li & 127;
                float4 v = *(const float4*)(hprev + (size_t)b * HH + (c4 << 2));
                *(float4*)&Hs[b * SW + (c4 << 2)] = v;
            }
        }
        __syncthreads();

        // Recurrent GEMM: warp w -> gate rows 2w,2w+1; lane l -> batches l,l+32
        float4 f00 = make_float4(0.f, 0.f, 0.f, 0.f);
        float4 f01 = f00, f10 = f00, f11 = f00;
        if (t > 0) {
            const float* w0p = &Ws[r0 * SW];
            const float* w1p = &Ws[r1 * SW];
            const float* h0p = &Hs[l        * SW];
            const float* h1p = &Hs[(l + 32) * SW];
#pragma unroll 8
            for (int k = 0; k < HH; k += 4) {
                float4 w0 = *(const float4*)(w0p + k);   // warp-uniform bcast
                float4 w1 = *(const float4*)(w1p + k);   // warp-uniform bcast
                float4 h0 = *(const float4*)(h0p + k);   // conflict-free
                float4 h1 = *(const float4*)(h1p + k);   // conflict-free
                f00.x += w0.x*h0.x; f00.y += w0.y*h0.y; f00.z += w0.z*h0.z; f00.w += w0.w*h0.w;
                f01.x += w0.x*h1.x; f01.y += w0.y*h1.y; f01.z += w0.z*h1.z; f01.w += w0.w*h1.w;
                f10.x += w1.x*h0.x; f10.y += w1.y*h0.y; f10.z += w1.z*h0.z; f10.w += w1.w*h0.w;
                f11.x += w1.x*h1.x; f11.y += w1.y*h1.y; f11.z += w1.z*h1.z; f11.w += w1.w*h1.w;
            }
        }

        // Stage gates = recurrent + xg
        {
            const float* xgt = xg + (size_t)t * BB * GG;
            Gs[r0 * 66 + l]      = (f00.x + f00.y + f00.z + f00.w) + xgt[(size_t)l        * GG + gr0];
            Gs[r0 * 66 + l + 32] = (f01.x + f01.y + f01.z + f01.w) + xgt[(size_t)(l + 32) * GG + gr0];
            Gs[r1 * 66 + l]      = (f10.x + f10.y + f10.z + f10.w) + xgt[(size_t)l        * GG + gr1];
            Gs[r1 * 66 + l + 32] = (f11.x + f11.y + f11.z + f11.w) + xgt[(size_t)(l + 32) * GG + gr1];
        }
        __syncthreads();

        // Pointwise cell/hidden update: one thread per (unit pv, batch pb)
        {
            float xi = Gs[(pv)      * 66 + pb];
            float xf = Gs[(4 + pv)  * 66 + pb];
            float xz = Gs[(8 + pv)  * 66 + pb];
            float xo = Gs[(12 + pv) * 66 + pb];
            float ig = 1.f / (1.f + expf(-xi));
            float fg = 1.f / (1.f + expf(-xf));
            float zg = tanhf(xz);
            float og = 1.f / (1.f + expf(-xo));
            float cn = fg * creg + ig * zg;
            creg = cn;
            float hn = og * tanhf(cn);
            h_all[(size_t)t * BB * HH + (size_t)pb * HH + (u0 + pv)] = hn;
        }

        // Publish h(t): fence, CTA-sync, then arrive on the grid barrier
        __threadfence();
        __syncthreads();
        if (tid == 0) atomicAdd(&g_bar, 1u);
    }

    // End-of-kernel reset so the next launch / graph replay starts clean.
    // Every CTA has passed its last spin before incrementing g_done, so the
    // last CTA can safely zero both counters.
    __syncthreads();
    if (tid == 0) {
        unsigned d = atomicAdd(&g_done, 1u);
        if (d == (unsigned)(NCTA - 1)) {
            g_bar = 0u;
            __threadfence();
            g_done = 0u;
        }
    }
}

// ---------------- output projection + sigmoid -------------------------------
__global__ void __launch_bounds__(256) out_proj(
    const float* __restrict__ h, const float* __restrict__ Wout,
    const float* __restrict__ bout, float* __restrict__ out)
{
    int row = blockIdx.x * 8 + (threadIdx.x >> 5);
    int l   = threadIdx.x & 31;
    const float* hp = h + (size_t)row * HH;
    float s = 0.f;
#pragma unroll
    for (int i = 0; i < 4; i++) {
        float4 a  = *(const float4*)(hp   + l * 4 + i * 128);
        float4 wv = *(const float4*)(Wout + l * 4 + i * 128);
        s += a.x * wv.x + a.y * wv.y + a.z * wv.z + a.w * wv.w;
    }
#pragma unroll
    for (int o = 16; o > 0; o >>= 1) s += __shfl_xor_sync(0xffffffffu, s, o);
    if (l == 0) out[row] = 1.f / (1.f + expf(-(s + bout[0])));
}

// ---------------- launch -----------------------------------------------------
extern "C" void kernel_launch(void* const* d_in, const int* in_sizes, int n_in,
                              void* d_out, int out_size)
{
    const float* input = (const float*)d_in[0];
    const float* W_ih1 = (const float*)d_in[1];
    const float* W_hh1 = (const float*)d_in[2];
    const float* b_ih1 = (const float*)d_in[3];
    const float* b_hh1 = (const float*)d_in[4];
    const float* W_ih2 = (const float*)d_in[5];
    const float* W_hh2 = (const float*)d_in[6];
    const float* b_ih2 = (const float*)d_in[7];
    const float* b_hh2 = (const float*)d_in[8];
    const float* W_out = (const float*)d_in[9];
    const float* b_out = (const float*)d_in[10];
    float* out = (float*)d_out;

    float *xg, *h;
    cudaGetSymbolAddress((void**)&xg, g_xg);
    cudaGetSymbolAddress((void**)&h,  g_h);
    cudaFuncSetAttribute(lstm_layer, cudaFuncAttributeMaxDynamicSharedMemorySize,
                         (int)SMEM_LSTM);

    dim3 gdim(GG / 128, (TT * BB) / 128);   // (16, 1024)

    // Layer 1
    gemm_xg<<<gdim, 256>>>(input, W_ih1, b_ih1, b_hh1, xg, TT * BB, GG, IN1);
    lstm_layer<<<NCTA, 256, SMEM_LSTM>>>(W_hh1, h, xg);

    // Layer 2 (xg buffer reused; h buffer switches from h1 history to h2 history)
    gemm_xg<<<gdim, 256>>>(h, W_ih2, b_ih2, b_hh2, xg, TT * BB, GG, HH);
    lstm_layer<<<NCTA, 256, SMEM_LSTM>>>(W_hh2, h, xg);

    out_proj<<<(TT * BB) / 8, 256>>>(h, W_out, b_out, out);
}

// round 4
// speedup vs baseline: 1.1575x; 1.1575x over previous
#include <cuda_runtime.h>
#include <cuda_fp16.h>
#include <math.h>
#include <stdint.h>

#define TT 2048
#define BB 64
#define IN1 256
#define HH 512
#define GG 2048   // 4*HH
#define NCTA 16   // persistent LSTM CTAs (each owns 32 hidden units)

// ---------------- scratch (static device globals; allocation-free) ----------
__device__ float  g_xg[(size_t)TT * GG * BB];   // 1 GB: xg transposed [t][g][b]
__device__ __half g_h [(size_t)TT * BB * HH];   // 128 MB: h history (fp16)
__device__ unsigned g_bar;                      // grid barrier arrival counter
__device__ unsigned g_done;                     // end-of-kernel reset counter

// ======================= helpers ============================================
__device__ __forceinline__ uint32_t s2u(const void* p) {
    uint32_t a;
    asm("{ .reg .u64 t; cvta.to.shared.u64 t, %1; cvt.u32.u64 %0, t; }"
        : "=r"(a) : "l"(p));
    return a;
}
__device__ __forceinline__ void ldsm_x4(uint32_t a, uint32_t& r0, uint32_t& r1,
                                        uint32_t& r2, uint32_t& r3) {
    asm volatile("ldmatrix.sync.aligned.m8n8.x4.shared.b16 {%0,%1,%2,%3}, [%4];"
                 : "=r"(r0), "=r"(r1), "=r"(r2), "=r"(r3) : "r"(a));
}
__device__ __forceinline__ void mma16816(float* c, uint32_t a0, uint32_t a1,
                                         uint32_t a2, uint32_t a3,
                                         uint32_t b0, uint32_t b1) {
    asm volatile(
        "mma.sync.aligned.m16n8k16.row.col.f32.f16.f16.f32 "
        "{%0,%1,%2,%3}, {%4,%5,%6,%7}, {%8,%9}, {%0,%1,%2,%3};"
        : "+f"(c[0]), "+f"(c[1]), "+f"(c[2]), "+f"(c[3])
        : "r"(a0), "r"(a1), "r"(a2), "r"(a3), "r"(b0), "r"(b1));
}
__device__ __forceinline__ float sigf(float x) {
    return __fdividef(1.f, 1.f + __expf(-x));
}
__device__ __forceinline__ float tanf_(float x) {
    return 1.f - __fdividef(2.f, __expf(2.f * x) + 1.f);
}

// ---------------- GEMM: xg_T[t][g][b] = A[tb,:]·W[g,:]^T + b1[g] + b2[g] ----
template <int AHALF>
__global__ void __launch_bounds__(256) gemm_xg(
    const void* __restrict__ Av, const float* __restrict__ W,
    const float* __restrict__ b1, const float* __restrict__ b2,
    float* __restrict__ C, int M, int N, int K)
{
    __shared__ float As[16][132];
    __shared__ float Bs[16][132];
    const int bm = blockIdx.y * 128;
    const int bn = blockIdx.x * 128;
    const int tid = threadIdx.x;
    const int tx = tid & 15;
    const int ty = tid >> 4;

    float acc[8][8];
#pragma unroll
    for (int i = 0; i < 8; i++)
#pragma unroll
        for (int j = 0; j < 8; j++) acc[i][j] = 0.f;

    for (int k0 = 0; k0 < K; k0 += 16) {
#pragma unroll
        for (int i = 0; i < 2; i++) {
            int li  = tid + i * 256;
            int row = li >> 2;
            int kc  = (li & 3) << 2;
            float4 va;
            if (AHALF) {
                const __half* A = (const __half*)Av;
                __half2 p0 = *(const __half2*)(A + (size_t)(bm + row) * K + k0 + kc);
                __half2 p1 = *(const __half2*)(A + (size_t)(bm + row) * K + k0 + kc + 2);
                va = make_float4(__low2float(p0), __high2float(p0),
                                 __low2float(p1), __high2float(p1));
            } else {
                const float* A = (const float*)Av;
                va = *(const float4*)(A + (size_t)(bm + row) * K + k0 + kc);
            }
            As[kc+0][row] = va.x; As[kc+1][row] = va.y;
            As[kc+2][row] = va.z; As[kc+3][row] = va.w;
            float4 vb = *(const float4*)(W + (size_t)(bn + row) * K + k0 + kc);
            Bs[kc+0][row] = vb.x; Bs[kc+1][row] = vb.y;
            Bs[kc+2][row] = vb.z; Bs[kc+3][row] = vb.w;
        }
        __syncthreads();
#pragma unroll
        for (int k = 0; k < 16; k++) {
            float a[8], b[8];
            *(float4*)&a[0] = *(float4*)&As[k][ty * 8];
            *(float4*)&a[4] = *(float4*)&As[k][ty * 8 + 4];
            *(float4*)&b[0] = *(float4*)&Bs[k][tx * 8];
            *(float4*)&b[4] = *(float4*)&Bs[k][tx * 8 + 4];
#pragma unroll
            for (int i = 0; i < 8; i++)
#pragma unroll
                for (int j = 0; j < 8; j++) acc[i][j] += a[i] * b[j];
        }
        __syncthreads();
    }

    // Transposed epilogue: C[t][g][b], t = row/64, b = row%64
#pragma unroll
    for (int i = 0; i < 8; i++) {
        int row = bm + ty * 8 + i;
        int t = row >> 6, b = row & 63;
#pragma unroll
        for (int j = 0; j < 8; j++) {
            int col = bn + tx * 8 + j;
            C[(size_t)t * N * 64 + (size_t)col * 64 + b] = acc[i][j] + b1[col] + b2[col];
        }
    }
}

// ---------------- persistent HMMA LSTM layer --------------------------------
// 16 CTAs; CTA owns units [32*bx, 32*bx+32). A = 128 W_hh gate rows fp16
// (resident in SMEM, padded rows), B = h(t-1) fp16 (reloaded per step).
// MMA: M=128, N=64, K=512 via mma.sync.m16n8k16.
// A-tile row r = 4*v + q  <->  W_hh row q*512 + u0 + v  (q = i,f,g,o)
// => warp w (rows 16w..16w+15) holds ALL gates of units 4w..4w+3.
#define APAD   520                    // halfs per A/B row (512 + 8 pad)
#define A_OFF  0                      // 128 x APAD fp16 = 133120 B
#define B_OFF  133120                 // 64 x APAD fp16 = 66560 B (reused as Gs)
#define HST_OFF 199680                // h(t) staging: 64 x 32 fp16 = 4096 B
#define SMEM_TOT 203776
#define GQ 288                        // Gs stride per gate q (floats)
#define GV 72                         // Gs stride per unit v (floats)
#define GW 1152                       // Gs stride per warp (floats)

__global__ void __launch_bounds__(256) lstm_layer_mma(
    const float* __restrict__ Whh,   // (2048, 512) fp32
    __half* __restrict__ h_all,      // (T, B, H) fp16: read t-1, write t
    const float* __restrict__ xg)    // (T, 4H, B) fp32 transposed x-gates
{
    extern __shared__ char sm[];
    const uint32_t sb = s2u(sm);
    const int tid = threadIdx.x;
    const int w   = tid >> 5;
    const int lane = tid & 31;
    const int u0  = blockIdx.x * 32;

    __half* Asm = (__half*)(sm + A_OFF);
    __half* Bsm = (__half*)(sm + B_OFF);
    __half* hst = (__half*)(sm + HST_OFF);

    // ---- one-time: W slice fp32->fp16, rows interleaved r = 4v + q ----
#pragma unroll
    for (int i = 0; i < 32; i++) {
        int c = tid + i * 256;               // 0..8191 (8-half chunks)
        int r = c >> 6, ic = c & 63;         // row 0..127, chunk 0..63
        int g = (r & 3) * 512 + u0 + (r >> 2);
        float4 f0 = *(const float4*)(Whh + (size_t)g * HH + ic * 8);
        float4 f1 = *(const float4*)(Whh + (size_t)g * HH + ic * 8 + 4);
        __half2 h01 = __floats2half2_rn(f0.x, f0.y);
        __half2 h23 = __floats2half2_rn(f0.z, f0.w);
        __half2 h45 = __floats2half2_rn(f1.x, f1.y);
        __half2 h67 = __floats2half2_rn(f1.z, f1.w);
        uint4 hv;
        hv.x = *reinterpret_cast<uint32_t*>(&h01);
        hv.y = *reinterpret_cast<uint32_t*>(&h23);
        hv.z = *reinterpret_cast<uint32_t*>(&h45);
        hv.w = *reinterpret_cast<uint32_t*>(&h67);
        *(uint4*)(Asm + r * APAD + ic * 8) = hv;
    }
    __syncthreads();

    // ldmatrix lane address patterns (bytes, shared space)
    const uint32_t aAddr0 = sb + A_OFF + (uint32_t)(16 * w + (lane & 15)) * (APAD * 2)
                          + ((lane >> 4) & 1) * 16;
    const uint32_t bAddr0 = sb + B_OFF + (uint32_t)(lane & 15) * (APAD * 2)
                          + ((lane >> 4) & 1) * 16;

    // gate staging (reuses B region after MMA): warp-local slice
    float* gw = (float*)(sm + B_OFF) + w * GW;
    // pointwise ownership: unit v_l = lane>>3 (0..3), batches [pb0, pb0+8)
    const int pv  = lane >> 3;
    const int pb0 = (lane & 7) * 8;
    const int ug  = u0 + 4 * w + pv;      // global unit for pointwise
    float creg[8];
#pragma unroll
    for (int j = 0; j < 8; j++) creg[j] = 0.f;

    for (int t = 0; t < TT; t++) {
        if (t > 0) {
            // wait for h(t-1) from all CTAs
            if (tid == 0) {
                unsigned tgt = (unsigned)NCTA * (unsigned)t;
                while (*(volatile unsigned*)&g_bar < tgt) __nanosleep(32);
            }
            __syncthreads();
            __threadfence();   // acquire

            const __half* hp = h_all + (size_t)(t - 1) * BB * HH;
#pragma unroll
            for (int i = 0; i < 16; i++) {
                int c = tid + i * 256;       // 0..4095 (8-half chunks)
                int b = c >> 6, ic = c & 63;
                uint4 v = *(const uint4*)(hp + (size_t)b * HH + ic * 8);
                *(uint4*)(Bsm + b * APAD + ic * 8) = v;
            }
            __syncthreads();
        }

        // ---- recurrent GEMM: c[nt][4] = W(16 rows) x h(64 cols) ----
        float cfr[8][4];
#pragma unroll
        for (int nt = 0; nt < 8; nt++)
#pragma unroll
            for (int j = 0; j < 4; j++) cfr[nt][j] = 0.f;

        if (t > 0) {
#pragma unroll
            for (int kt = 0; kt < 32; kt++) {
                uint32_t a0, a1, a2, a3;
                ldsm_x4(aAddr0 + kt * 32, a0, a1, a2, a3);
#pragma unroll
                for (int np = 0; np < 4; np++) {
                    uint32_t b0, b1, b2, b3;
                    ldsm_x4(bAddr0 + kt * 32 + np * 16 * (APAD * 2),
                            b0, b1, b2, b3);
                    mma16816(cfr[2 * np],     a0, a1, a2, a3, b0, b2);
                    mma16816(cfr[2 * np + 1], a0, a1, a2, a3, b1, b3);
                }
            }
        }
        __syncthreads();   // all warps done reading Bsm -> safe to reuse as Gs

        // ---- stage gates into warp-local SMEM: [q][v][b] ----
        {
            int q  = (lane >> 2) & 3;
            int v0 = lane >> 4;            // 0 or 1; rows +8 -> v0+2
            int cb = 2 * (lane & 3);
#pragma unroll
            for (int nt = 0; nt < 8; nt++) {
                int b = nt * 8 + cb;
                *(float2*)(gw + q * GQ + v0 * GV + b)       = make_float2(cfr[nt][0], cfr[nt][1]);
                *(float2*)(gw + q * GQ + (v0 + 2) * GV + b) = make_float2(cfr[nt][2], cfr[nt][3]);
            }
        }
        __syncwarp();

        // ---- pointwise: gates = Gs + xg_T; c in regs; h -> hst fp16 ----
        {
            const float* xt = xg + (size_t)t * GG * 64;
            const float* xi = xt + (size_t)ug          * 64 + pb0;
            const float* xf = xt + (size_t)(ug +  512) * 64 + pb0;
            const float* xz = xt + (size_t)(ug + 1024) * 64 + pb0;
            const float* xo = xt + (size_t)(ug + 1536) * 64 + pb0;
            const float* gi = gw + 0 * GQ + pv * GV + pb0;
            const float* gf = gw + 1 * GQ + pv * GV + pb0;
            const float* gz = gw + 2 * GQ + pv * GV + pb0;
            const float* go = gw + 3 * GQ + pv * GV + pb0;
#pragma unroll
            for (int j = 0; j < 8; j++) {
                float ai = gi[j] + xi[j];
                float af = gf[j] + xf[j];
                float az = gz[j] + xz[j];
                float ao = go[j] + xo[j];
                float cn = sigf(af) * creg[j] + sigf(ai) * tanf_(az);
                creg[j] = cn;
                float hn = sigf(ao) * tanf_(cn);
                hst[(pb0 + j) * 32 + 4 * w + pv] = __float2half(hn);
            }
        }
        __syncthreads();

        // ---- coalesced global store of h(t): 256 x 16B ----
        {
            int b = tid >> 2, part = tid & 3;
            uint4 v = *(const uint4*)((const char*)hst + b * 64 + part * 16);
            char* dst = (char*)(h_all + (size_t)t * BB * HH + (size_t)b * HH + u0)
                        + part * 16;
            *(uint4*)dst = v;
        }
        __threadfence();
        __syncthreads();
        if (tid == 0) atomicAdd(&g_bar, 1u);
    }

    // reset counters for next launch / graph replay
    __syncthreads();
    if (tid == 0) {
        unsigned d = atomicAdd(&g_done, 1u);
        if (d == (unsigned)(NCTA - 1)) {
            g_bar = 0u;
            __threadfence();
            g_done = 0u;
        }
    }
}

// ---------------- output projection + sigmoid (fp16 h) ----------------------
__global__ void __launch_bounds__(256) out_proj(
    const __half* __restrict__ h, const float* __restrict__ Wout,
    const float* __restrict__ bout, float* __restrict__ out)
{
    int row = blockIdx.x * 8 + (threadIdx.x >> 5);
    int l   = threadIdx.x & 31;
    const __half* hp = h + (size_t)row * HH;
    float s = 0.f;
#pragma unroll
    for (int i = 0; i < 2; i++) {
        uint4 hc = *(const uint4*)((const char*)hp + l * 32 + i * 16);
        const __half2* h2 = (const __half2*)&hc;
        float4 w0 = *(const float4*)(Wout + l * 16 + i * 8);
        float4 w1 = *(const float4*)(Wout + l * 16 + i * 8 + 4);
        s += __low2float(h2[0]) * w0.x + __high2float(h2[0]) * w0.y
           + __low2float(h2[1]) * w0.z + __high2float(h2[1]) * w0.w
           + __low2float(h2[2]) * w1.x + __high2float(h2[2]) * w1.y
           + __low2float(h2[3]) * w1.z + __high2float(h2[3]) * w1.w;
    }
#pragma unroll
    for (int o = 16; o > 0; o >>= 1) s += __shfl_xor_sync(0xffffffffu, s, o);
    if (l == 0) out[row] = 1.f / (1.f + expf(-(s + bout[0])));
}

// ---------------- launch -----------------------------------------------------
extern "C" void kernel_launch(void* const* d_in, const int* in_sizes, int n_in,
                              void* d_out, int out_size)
{
    const float* input = (const float*)d_in[0];
    const float* W_ih1 = (const float*)d_in[1];
    const float* W_hh1 = (const float*)d_in[2];
    const float* b_ih1 = (const float*)d_in[3];
    const float* b_hh1 = (const float*)d_in[4];
    const float* W_ih2 = (const float*)d_in[5];
    const float* W_hh2 = (const float*)d_in[6];
    const float* b_ih2 = (const float*)d_in[7];
    const float* b_hh2 = (const float*)d_in[8];
    const float* W_out = (const float*)d_in[9];
    const float* b_out = (const float*)d_in[10];
    float* out = (float*)d_out;

    float*  xg;
    __half* h;
    cudaGetSymbolAddress((void**)&xg, g_xg);
    cudaGetSymbolAddress((void**)&h,  g_h);
    cudaFuncSetAttribute(lstm_layer_mma, cudaFuncAttributeMaxDynamicSharedMemorySize,
                         SMEM_TOT);

    dim3 gdim(GG / 128, (TT * BB) / 128);   // (16, 1024)

    // Layer 1: xg from fp32 input; recurrence on HMMA tensor cores
    gemm_xg<0><<<gdim, 256>>>(input, W_ih1, b_ih1, b_hh1, xg, TT * BB, GG, IN1);
    lstm_layer_mma<<<NCTA, 256, SMEM_TOT>>>(W_hh1, h, xg);

    // Layer 2: xg from fp16 h1 history
    gemm_xg<1><<<gdim, 256>>>(h, W_ih2, b_ih2, b_hh2, xg, TT * BB, GG, HH);
    lstm_layer_mma<<<NCTA, 256, SMEM_TOT>>>(W_hh2, h, xg);

    out_proj<<<(TT * BB) / 8, 256>>>(h, W_out, b_out, out);
}

// round 6
// speedup vs baseline: 1.4941x; 1.2908x over previous
#include <cuda_runtime.h>
#include <cuda_fp16.h>
#include <math.h>
#include <stdint.h>

#define TT 2048
#define BB 64
#define IN1 256
#define HH 512
#define GG 2048   // 4*HH
#define NCTA 16   // persistent LSTM CTAs (each owns 32 hidden units)

// ---------------- scratch (static device globals; allocation-free) ----------
__device__ float  g_xg [(size_t)TT * GG * BB];   // 1 GB: xg transposed [t][g][b]
__device__ __half g_h  [(size_t)TT * BB * HH];   // 128 MB: h history (fp16)
__device__ __half g_x16[(size_t)TT * BB * IN1];  // 64 MB: fp16 input
__device__ __half g_w16[(size_t)GG * HH];        // 2 MB: fp16 W_ih (reused)
__device__ unsigned g_bar;                       // grid barrier arrival counter
__device__ unsigned g_done;                      // end-of-kernel reset counter

// ======================= helpers ============================================
__device__ __forceinline__ uint32_t s2u(const void* p) {
    uint32_t a;
    asm("{ .reg .u64 t; cvta.to.shared.u64 t, %1; cvt.u32.u64 %0, t; }"
        : "=r"(a) : "l"(p));
    return a;
}
__device__ __forceinline__ void ldsm_x4(uint32_t a, uint32_t& r0, uint32_t& r1,
                                        uint32_t& r2, uint32_t& r3) {
    asm volatile("ldmatrix.sync.aligned.m8n8.x4.shared.b16 {%0,%1,%2,%3}, [%4];"
                 : "=r"(r0), "=r"(r1), "=r"(r2), "=r"(r3) : "r"(a));
}
__device__ __forceinline__ void mma16816(float* c, uint32_t a0, uint32_t a1,
                                         uint32_t a2, uint32_t a3,
                                         uint32_t b0, uint32_t b1) {
    asm volatile(
        "mma.sync.aligned.m16n8k16.row.col.f32.f16.f16.f32 "
        "{%0,%1,%2,%3}, {%4,%5,%6,%7}, {%8,%9}, {%0,%1,%2,%3};"
        : "+f"(c[0]), "+f"(c[1]), "+f"(c[2]), "+f"(c[3])
        : "r"(a0), "r"(a1), "r"(a2), "r"(a3), "r"(b0), "r"(b1));
}
__device__ __forceinline__ void cp16(uint32_t saddr, const void* g) {
    asm volatile("cp.async.cg.shared.global [%0], [%1], 16;"
                 :: "r"(saddr), "l"(g));
}
#define CP_COMMIT() asm volatile("cp.async.commit_group;" ::: "memory")
#define CP_WAIT1()  asm volatile("cp.async.wait_group 1;" ::: "memory")
__device__ __forceinline__ float sigf(float x) {
    return __fdividef(1.f, 1.f + __expf(-x));
}
__device__ __forceinline__ float tanf_(float x) {
    return 1.f - __fdividef(2.f, __expf(2.f * x) + 1.f);
}

// ---------------- fp32 -> fp16 conversion ----------------------------------
__global__ void __launch_bounds__(256) f32to16(const float* __restrict__ src,
                                               __half* __restrict__ dst) {
    size_t i = ((size_t)blockIdx.x * 256 + threadIdx.x) * 8;
    float4 a = *(const float4*)(src + i);
    float4 b = *(const float4*)(src + i + 4);
    __half2 h0 = __floats2half2_rn(a.x, a.y);
    __half2 h1 = __floats2half2_rn(a.z, a.w);
    __half2 h2 = __floats2half2_rn(b.x, b.y);
    __half2 h3 = __floats2half2_rn(b.z, b.w);
    uint4 v;
    v.x = *reinterpret_cast<uint32_t*>(&h0);
    v.y = *reinterpret_cast<uint32_t*>(&h1);
    v.z = *reinterpret_cast<uint32_t*>(&h2);
    v.w = *reinterpret_cast<uint32_t*>(&h3);
    *(uint4*)(dst + i) = v;
}

// ---------------- HMMA GEMM: xg_T[t][g][b] = A[m,:]·W[g,:]^T + b1 + b2 ------
// M = TT*BB (rows m = t*64+b), N = GG, fp16 inputs, fp32 accum.
// CTA tile 128(M) x 128(N), K-chunk 64, double-buffered cp.async.
// Warp layout: wm = w&1 (64 M-rows), wn = w>>1 (32 N-cols).
#define KC    64
#define RS    144                       // SMEM row stride bytes (64+8 halfs)
#define STG   (128 * RS)                // 18432 B per tile stage
#define HG_SMEM (4 * STG)               // A[2] + B[2]

template <int K>
__global__ void __launch_bounds__(256) hgemm_xg(
    const __half* __restrict__ A, const __half* __restrict__ W,
    const float* __restrict__ b1, const float* __restrict__ b2,
    float* __restrict__ C)
{
    extern __shared__ char sm[];
    const uint32_t sbA = s2u(sm);
    const uint32_t sbB = sbA + 2 * STG;
    const int tid  = threadIdx.x;
    const int w    = tid >> 5;
    const int lane = tid & 31;
    const int wm   = w & 1;
    const int wn   = w >> 1;
    const int bm   = blockIdx.y * 128;
    const int bn   = blockIdx.x * 128;

    // per-thread load mapping: 4 x 16B chunks per tile per stage
    const int lrow = tid >> 1;               // base row pattern (see loop)
    (void)lrow;

    float cacc[4][4][4];
#pragma unroll
    for (int mt = 0; mt < 4; mt++)
#pragma unroll
        for (int n8 = 0; n8 < 4; n8++)
#pragma unroll
            for (int j = 0; j < 4; j++) cacc[mt][n8][j] = 0.f;

    // bias per thread (8 columns)
    float bias[8];
#pragma unroll
    for (int n8 = 0; n8 < 4; n8++) {
        int g = bn + wn * 32 + n8 * 8 + 2 * (lane & 3);
        bias[2 * n8]     = b1[g] + b2[g];
        bias[2 * n8 + 1] = b1[g + 1] + b2[g + 1];
    }

    const int nK = K / KC;

    // ---- stage loader ----
    auto load_stage = [&](int kc, int s) {
#pragma unroll
        for (int p = 0; p < 4; p++) {
            int idx = tid + p * 256;          // 0..1023
            int row = idx >> 3;               // 0..127
            int c8  = idx & 7;                // 0..7
            cp16(sbA + s * STG + row * RS + c8 * 16,
                 A + (size_t)(bm + row) * K + kc * KC + c8 * 8);
            cp16(sbB + s * STG + row * RS + c8 * 16,
                 W + (size_t)(bn + row) * K + kc * KC + c8 * 8);
        }
    };

    load_stage(0, 0);
    CP_COMMIT();

    const uint32_t aBase0 = sbA + (uint32_t)(wm * 64 + (lane & 15)) * RS
                          + (lane >> 4) * 16;
    const uint32_t bBase0 = sbB + (uint32_t)(wn * 32 + (lane & 15)) * RS
                          + (lane >> 4) * 16;

    for (int kc = 0; kc < nK; kc++) {
        int s = kc & 1;
        if (kc + 1 < nK) load_stage(kc + 1, s ^ 1);
        CP_COMMIT();
        CP_WAIT1();
        __syncthreads();

        const uint32_t aB = aBase0 + s * STG;
        const uint32_t bB = bBase0 + s * STG;
#pragma unroll
        for (int kt = 0; kt < 4; kt++) {
            uint32_t a[4][4];
#pragma unroll
            for (int mt = 0; mt < 4; mt++)
                ldsm_x4(aB + mt * 16 * RS + kt * 32,
                        a[mt][0], a[mt][1], a[mt][2], a[mt][3]);
#pragma unroll
            for (int nt = 0; nt < 2; nt++) {
                uint32_t r0, r1, r2, r3;
                ldsm_x4(bB + nt * 16 * RS + kt * 32, r0, r1, r2, r3);
#pragma unroll
                for (int mt = 0; mt < 4; mt++) {
                    mma16816(cacc[mt][nt * 2],     a[mt][0], a[mt][1], a[mt][2], a[mt][3], r0, r2);
                    mma16816(cacc[mt][nt * 2 + 1], a[mt][0], a[mt][1], a[mt][2], a[mt][3], r1, r3);
                }
            }
        }
        __syncthreads();
    }

    // ---- transposed epilogue: C[t][g][b] = acc + bias ----
#pragma unroll
    for (int mt = 0; mt < 4; mt++) {
        int m0 = bm + wm * 64 + mt * 16 + (lane >> 2);
        int m1 = m0 + 8;
        size_t base0 = (size_t)(m0 >> 6) * GG * 64 + (m0 & 63);
        size_t base1 = (size_t)(m1 >> 6) * GG * 64 + (m1 & 63);
#pragma unroll
        for (int n8 = 0; n8 < 4; n8++) {
            int g = bn + wn * 32 + n8 * 8 + 2 * (lane & 3);
            const float* cf = cacc[mt][n8];
            C[base0 + (size_t)g * 64]       = cf[0] + bias[2 * n8];
            C[base0 + (size_t)(g + 1) * 64] = cf[1] + bias[2 * n8 + 1];
            C[base1 + (size_t)g * 64]       = cf[2] + bias[2 * n8];
            C[base1 + (size_t)(g + 1) * 64] = cf[3] + bias[2 * n8 + 1];
        }
    }
}

// ---------------- persistent HMMA LSTM layer (unchanged from R4) ------------
#define APAD   520
#define A_OFF  0
#define B_OFF  133120
#define HST_OFF 199680
#define SMEM_TOT 203776
#define GQ 288
#define GV 72
#define GW 1152

__global__ void __launch_bounds__(256) lstm_layer_mma(
    const float* __restrict__ Whh,   // (2048, 512) fp32
    __half* __restrict__ h_all,      // (T, B, H) fp16: read t-1, write t
    const float* __restrict__ xg)    // (T, 4H, B) fp32 transposed x-gates
{
    extern __shared__ char sm[];
    const uint32_t sb = s2u(sm);
    const int tid = threadIdx.x;
    const int w   = tid >> 5;
    const int lane = tid & 31;
    const int u0  = blockIdx.x * 32;

    __half* Asm = (__half*)(sm + A_OFF);
    __half* Bsm = (__half*)(sm + B_OFF);
    __half* hst = (__half*)(sm + HST_OFF);

    // one-time: W slice fp32->fp16, rows interleaved r = 4v + q
#pragma unroll
    for (int i = 0; i < 32; i++) {
        int c = tid + i * 256;
        int r = c >> 6, ic = c & 63;
        int g = (r & 3) * 512 + u0 + (r >> 2);
        float4 f0 = *(const float4*)(Whh + (size_t)g * HH + ic * 8);
        float4 f1 = *(const float4*)(Whh + (size_t)g * HH + ic * 8 + 4);
        __half2 h01 = __floats2half2_rn(f0.x, f0.y);
        __half2 h23 = __floats2half2_rn(f0.z, f0.w);
        __half2 h45 = __floats2half2_rn(f1.x, f1.y);
        __half2 h67 = __floats2half2_rn(f1.z, f1.w);
        uint4 hv;
        hv.x = *reinterpret_cast<uint32_t*>(&h01);
        hv.y = *reinterpret_cast<uint32_t*>(&h23);
        hv.z = *reinterpret_cast<uint32_t*>(&h45);
        hv.w = *reinterpret_cast<uint32_t*>(&h67);
        *(uint4*)(Asm + r * APAD + ic * 8) = hv;
    }
    __syncthreads();

    const uint32_t aAddr0 = sb + A_OFF + (uint32_t)(16 * w + (lane & 15)) * (APAD * 2)
                          + ((lane >> 4) & 1) * 16;
    const uint32_t bAddr0 = sb + B_OFF + (uint32_t)(lane & 15) * (APAD * 2)
                          + ((lane >> 4) & 1) * 16;

    float* gw = (float*)(sm + B_OFF) + w * GW;
    const int pv  = lane >> 3;
    const int pb0 = (lane & 7) * 8;
    const int ug  = u0 + 4 * w + pv;
    float creg[8];
#pragma unroll
    for (int j = 0; j < 8; j++) creg[j] = 0.f;

    for (int t = 0; t < TT; t++) {
        if (t > 0) {
            if (tid == 0) {
                unsigned tgt = (unsigned)NCTA * (unsigned)t;
                while (*(volatile unsigned*)&g_bar < tgt) __nanosleep(32);
            }
            __syncthreads();
            __threadfence();

            const __half* hp = h_all + (size_t)(t - 1) * BB * HH;
#pragma unroll
            for (int i = 0; i < 16; i++) {
                int c = tid + i * 256;
                int b = c >> 6, ic = c & 63;
                uint4 v = *(const uint4*)(hp + (size_t)b * HH + ic * 8);
                *(uint4*)(Bsm + b * APAD + ic * 8) = v;
            }
            __syncthreads();
        }

        float cfr[8][4];
#pragma unroll
        for (int nt = 0; nt < 8; nt++)
#pragma unroll
            for (int j = 0; j < 4; j++) cfr[nt][j] = 0.f;

        if (t > 0) {
#pragma unroll
            for (int kt = 0; kt < 32; kt++) {
                uint32_t a0, a1, a2, a3;
                ldsm_x4(aAddr0 + kt * 32, a0, a1, a2, a3);
#pragma unroll
                for (int np = 0; np < 4; np++) {
                    uint32_t b0, b1, b2, b3;
                    ldsm_x4(bAddr0 + kt * 32 + np * 16 * (APAD * 2),
                            b0, b1, b2, b3);
                    mma16816(cfr[2 * np],     a0, a1, a2, a3, b0, b2);
                    mma16816(cfr[2 * np + 1], a0, a1, a2, a3, b1, b3);
                }
            }
        }
        __syncthreads();

        {
            int q  = (lane >> 2) & 3;
            int v0 = lane >> 4;
            int cb = 2 * (lane & 3);
#pragma unroll
            for (int nt = 0; nt < 8; nt++) {
                int b = nt * 8 + cb;
                *(float2*)(gw + q * GQ + v0 * GV + b)       = make_float2(cfr[nt][0], cfr[nt][1]);
                *(float2*)(gw + q * GQ + (v0 + 2) * GV + b) = make_float2(cfr[nt][2], cfr[nt][3]);
            }
        }
        __syncwarp();

        {
            const float* xt = xg + (size_t)t * GG * 64;
            const float* xi = xt + (size_t)ug          * 64 + pb0;
            const float* xf = xt + (size_t)(ug +  512) * 64 + pb0;
            const float* xz = xt + (size_t)(ug + 1024) * 64 + pb0;
            const float* xo = xt + (size_t)(ug + 1536) * 64 + pb0;
            const float* gi = gw + 0 * GQ + pv * GV + pb0;
            const float* gf = gw + 1 * GQ + pv * GV + pb0;
            const float* gz = gw + 2 * GQ + pv * GV + pb0;
            const float* go = gw + 3 * GQ + pv * GV + pb0;
#pragma unroll
            for (int j = 0; j < 8; j++) {
                float ai = gi[j] + xi[j];
                float af = gf[j] + xf[j];
                float az = gz[j] + xz[j];
                float ao = go[j] + xo[j];
                float cn = sigf(af) * creg[j] + sigf(ai) * tanf_(az);
                creg[j] = cn;
                float hn = sigf(ao) * tanf_(cn);
                hst[(pb0 + j) * 32 + 4 * w + pv] = __float2half(hn);
            }
        }
        __syncthreads();

        {
            int b = tid >> 2, part = tid & 3;
            uint4 v = *(const uint4*)((const char*)hst + b * 64 + part * 16);
            char* dst = (char*)(h_all + (size_t)t * BB * HH + (size_t)b * HH + u0)
                        + part * 16;
            *(uint4*)dst = v;
        }
        __threadfence();
        __syncthreads();
        if (tid == 0) atomicAdd(&g_bar, 1u);
    }

    __syncthreads();
    if (tid == 0) {
        unsigned d = atomicAdd(&g_done, 1u);
        if (d == (unsigned)(NCTA - 1)) {
            g_bar = 0u;
            __threadfence();
            g_done = 0u;
        }
    }
}

// ---------------- output projection + sigmoid (fp16 h) ----------------------
__global__ void __launch_bounds__(256) out_proj(
    const __half* __restrict__ h, const float* __restrict__ Wout,
    const float* __restrict__ bout, float* __restrict__ out)
{
    int row = blockIdx.x * 8 + (threadIdx.x >> 5);
    int l   = threadIdx.x & 31;
    const __half* hp = h + (size_t)row * HH;
    float s = 0.f;
#pragma unroll
    for (int i = 0; i < 2; i++) {
        uint4 hc = *(const uint4*)((const char*)hp + l * 32 + i * 16);
        const __half2* h2 = (const __half2*)&hc;
        float4 w0 = *(const float4*)(Wout + l * 16 + i * 8);
        float4 w1 = *(const float4*)(Wout + l * 16 + i * 8 + 4);
        s += __low2float(h2[0]) * w0.x + __high2float(h2[0]) * w0.y
           + __low2float(h2[1]) * w0.z + __high2float(h2[1]) * w0.w
           + __low2float(h2[2]) * w1.x + __high2float(h2[2]) * w1.y
           + __low2float(h2[3]) * w1.z + __high2float(h2[3]) * w1.w;
    }
#pragma unroll
    for (int o = 16; o > 0; o >>= 1) s += __shfl_xor_sync(0xffffffffu, s, o);
    if (l == 0) out[row] = 1.f / (1.f + expf(-(s + bout[0])));
}

// ---------------- launch -----------------------------------------------------
extern "C" void kernel_launch(void* const* d_in, const int* in_sizes, int n_in,
                              void* d_out, int out_size)
{
    const float* input = (const float*)d_in[0];
    const float* W_ih1 = (const float*)d_in[1];
    const float* W_hh1 = (const float*)d_in[2];
    const float* b_ih1 = (const float*)d_in[3];
    const float* b_hh1 = (const float*)d_in[4];
    const float* W_ih2 = (const float*)d_in[5];
    const float* W_hh2 = (const float*)d_in[6];
    const float* b_ih2 = (const float*)d_in[7];
    const float* b_hh2 = (const float*)d_in[8];
    const float* W_out = (const float*)d_in[9];
    const float* b_out = (const float*)d_in[10];
    float* out = (float*)d_out;

    float*  xg;
    __half* h;
    __half* x16;
    __half* w16;
    cudaGetSymbolAddress((void**)&xg,  g_xg);
    cudaGetSymbolAddress((void**)&h,   g_h);
    cudaGetSymbolAddress((void**)&x16, g_x16);
    cudaGetSymbolAddress((void**)&w16, g_w16);

    cudaFuncSetAttribute(lstm_layer_mma, cudaFuncAttributeMaxDynamicSharedMemorySize,
                         SMEM_TOT);
    cudaFuncSetAttribute(hgemm_xg<IN1>, cudaFuncAttributeMaxDynamicSharedMemorySize,
                         HG_SMEM);
    cudaFuncSetAttribute(hgemm_xg<HH>,  cudaFuncAttributeMaxDynamicSharedMemorySize,
                         HG_SMEM);

    dim3 hg(GG / 128, (TT * BB) / 128);   // (16, 1024)

    // Layer 1: convert input + W_ih1 to fp16, HMMA xg GEMM, HMMA recurrence
    f32to16<<<(TT * BB * IN1) / 2048, 256>>>(input, x16);
    f32to16<<<(GG * IN1) / 2048, 256>>>(W_ih1, w16);
    hgemm_xg<IN1><<<hg, 256, HG_SMEM>>>(x16, w16, b_ih1, b_hh1, xg);
    lstm_layer_mma<<<NCTA, 256, SMEM_TOT>>>(W_hh1, h, xg);

    // Layer 2: A = fp16 h1 history
    f32to16<<<(GG * HH) / 2048, 256>>>(W_ih2, w16);
    hgemm_xg<HH><<<hg, 256, HG_SMEM>>>(h, w16, b_ih2, b_hh2, xg);
    lstm_layer_mma<<<NCTA, 256, SMEM_TOT>>>(W_hh2, h, xg);

    out_proj<<<(TT * BB) / 8, 256>>>(h, W_out, b_out, out);
}

// round 7
// speedup vs baseline: 2.3640x; 1.5822x over previous
#include <cuda_runtime.h>
#include <cuda_fp16.h>
#include <math.h>
#include <stdint.h>

#define TT 2048
#define BB 64
#define IN1 256
#define HH 512
#define GG 2048   // 4*HH
#define NC2 64    // persistent LSTM CTAs (each owns 8 hidden units)

// ---------------- scratch (static device globals; allocation-free) ----------
__device__ float  g_xg [(size_t)TT * GG * BB];   // 1 GB: xg transposed [t][g][b]
__device__ __half g_h  [(size_t)TT * BB * HH];   // 128 MB: h history (fp16)
__device__ __half g_x16[(size_t)TT * BB * IN1];  // 64 MB: fp16 input
__device__ __half g_w16[(size_t)GG * HH];        // 2 MB: fp16 W_ih (reused)
__device__ unsigned g_arrive[NC2 * 32];          // per-CTA step flags (padded)
__device__ unsigned g_done;                      // end-of-kernel reset counter

// ======================= helpers ============================================
__device__ __forceinline__ uint32_t s2u(const void* p) {
    uint32_t a;
    asm("{ .reg .u64 t; cvta.to.shared.u64 t, %1; cvt.u32.u64 %0, t; }"
        : "=r"(a) : "l"(p));
    return a;
}
__device__ __forceinline__ void ldsm_x4(uint32_t a, uint32_t& r0, uint32_t& r1,
                                        uint32_t& r2, uint32_t& r3) {
    asm volatile("ldmatrix.sync.aligned.m8n8.x4.shared.b16 {%0,%1,%2,%3}, [%4];"
                 : "=r"(r0), "=r"(r1), "=r"(r2), "=r"(r3) : "r"(a));
}
__device__ __forceinline__ void mma16816(float* c, uint32_t a0, uint32_t a1,
                                         uint32_t a2, uint32_t a3,
                                         uint32_t b0, uint32_t b1) {
    asm volatile(
        "mma.sync.aligned.m16n8k16.row.col.f32.f16.f16.f32 "
        "{%0,%1,%2,%3}, {%4,%5,%6,%7}, {%8,%9}, {%0,%1,%2,%3};"
        : "+f"(c[0]), "+f"(c[1]), "+f"(c[2]), "+f"(c[3])
        : "r"(a0), "r"(a1), "r"(a2), "r"(a3), "r"(b0), "r"(b1));
}
__device__ __forceinline__ void cp16(uint32_t saddr, const void* g) {
    asm volatile("cp.async.cg.shared.global [%0], [%1], 16;"
                 :: "r"(saddr), "l"(g));
}
#define CP_COMMIT() asm volatile("cp.async.commit_group;" ::: "memory")
#define CP_WAIT1()  asm volatile("cp.async.wait_group 1;" ::: "memory")
__device__ __forceinline__ float sigf(float x) {
    return __fdividef(1.f, 1.f + __expf(-x));
}
__device__ __forceinline__ float tanf_(float x) {
    return 1.f - __fdividef(2.f, __expf(2.f * x) + 1.f);
}

// ---------------- fp32 -> fp16 conversion ----------------------------------
__global__ void __launch_bounds__(256) f32to16(const float* __restrict__ src,
                                               __half* __restrict__ dst) {
    size_t i = ((size_t)blockIdx.x * 256 + threadIdx.x) * 8;
    float4 a = *(const float4*)(src + i);
    float4 b = *(const float4*)(src + i + 4);
    __half2 h0 = __floats2half2_rn(a.x, a.y);
    __half2 h1 = __floats2half2_rn(a.z, a.w);
    __half2 h2 = __floats2half2_rn(b.x, b.y);
    __half2 h3 = __floats2half2_rn(b.z, b.w);
    uint4 v;
    v.x = *reinterpret_cast<uint32_t*>(&h0);
    v.y = *reinterpret_cast<uint32_t*>(&h1);
    v.z = *reinterpret_cast<uint32_t*>(&h2);
    v.w = *reinterpret_cast<uint32_t*>(&h3);
    *(uint4*)(dst + i) = v;
}

// ---------------- HMMA GEMM: xg_T[t][g][b] = A[m,:]·W[g,:]^T + b1 + b2 ------
#define KC    64
#define RS    144
#define STG   (128 * RS)
#define HG_SMEM (4 * STG)

template <int K>
__global__ void __launch_bounds__(256) hgemm_xg(
    const __half* __restrict__ A, const __half* __restrict__ W,
    const float* __restrict__ b1, const float* __restrict__ b2,
    float* __restrict__ C)
{
    extern __shared__ char sm[];
    const uint32_t sbA = s2u(sm);
    const uint32_t sbB = sbA + 2 * STG;
    const int tid  = threadIdx.x;
    const int w    = tid >> 5;
    const int lane = tid & 31;
    const int wm   = w & 1;
    const int wn   = w >> 1;
    const int bm   = blockIdx.y * 128;
    const int bn   = blockIdx.x * 128;

    float cacc[4][4][4];
#pragma unroll
    for (int mt = 0; mt < 4; mt++)
#pragma unroll
        for (int n8 = 0; n8 < 4; n8++)
#pragma unroll
            for (int j = 0; j < 4; j++) cacc[mt][n8][j] = 0.f;

    float bias[8];
#pragma unroll
    for (int n8 = 0; n8 < 4; n8++) {
        int g = bn + wn * 32 + n8 * 8 + 2 * (lane & 3);
        bias[2 * n8]     = b1[g] + b2[g];
        bias[2 * n8 + 1] = b1[g + 1] + b2[g + 1];
    }

    const int nK = K / KC;

    auto load_stage = [&](int kc, int s) {
#pragma unroll
        for (int p = 0; p < 4; p++) {
            int idx = tid + p * 256;
            int row = idx >> 3;
            int c8  = idx & 7;
            cp16(sbA + s * STG + row * RS + c8 * 16,
                 A + (size_t)(bm + row) * K + kc * KC + c8 * 8);
            cp16(sbB + s * STG + row * RS + c8 * 16,
                 W + (size_t)(bn + row) * K + kc * KC + c8 * 8);
        }
    };

    load_stage(0, 0);
    CP_COMMIT();

    const uint32_t aBase0 = sbA + (uint32_t)(wm * 64 + (lane & 15)) * RS
                          + (lane >> 4) * 16;
    const uint32_t bBase0 = sbB + (uint32_t)(wn * 32 + (lane & 15)) * RS
                          + (lane >> 4) * 16;

    for (int kc = 0; kc < nK; kc++) {
        int s = kc & 1;
        if (kc + 1 < nK) load_stage(kc + 1, s ^ 1);
        CP_COMMIT();
        CP_WAIT1();
        __syncthreads();

        const uint32_t aB = aBase0 + s * STG;
        const uint32_t bB = bBase0 + s * STG;
#pragma unroll
        for (int kt = 0; kt < 4; kt++) {
            uint32_t a[4][4];
#pragma unroll
            for (int mt = 0; mt < 4; mt++)
                ldsm_x4(aB + mt * 16 * RS + kt * 32,
                        a[mt][0], a[mt][1], a[mt][2], a[mt][3]);
#pragma unroll
            for (int nt = 0; nt < 2; nt++) {
                uint32_t r0, r1, r2, r3;
                ldsm_x4(bB + nt * 16 * RS + kt * 32, r0, r1, r2, r3);
#pragma unroll
                for (int mt = 0; mt < 4; mt++) {
                    mma16816(cacc[mt][nt * 2],     a[mt][0], a[mt][1], a[mt][2], a[mt][3], r0, r2);
                    mma16816(cacc[mt][nt * 2 + 1], a[mt][0], a[mt][1], a[mt][2], a[mt][3], r1, r3);
                }
            }
        }
        __syncthreads();
    }

#pragma unroll
    for (int mt = 0; mt < 4; mt++) {
        int m0 = bm + wm * 64 + mt * 16 + (lane >> 2);
        int m1 = m0 + 8;
        size_t base0 = (size_t)(m0 >> 6) * GG * 64 + (m0 & 63);
        size_t base1 = (size_t)(m1 >> 6) * GG * 64 + (m1 & 63);
#pragma unroll
        for (int n8 = 0; n8 < 4; n8++) {
            int g = bn + wn * 32 + n8 * 8 + 2 * (lane & 3);
            const float* cf = cacc[mt][n8];
            C[base0 + (size_t)g * 64]       = cf[0] + bias[2 * n8];
            C[base0 + (size_t)(g + 1) * 64] = cf[1] + bias[2 * n8 + 1];
            C[base1 + (size_t)g * 64]       = cf[2] + bias[2 * n8];
            C[base1 + (size_t)(g + 1) * 64] = cf[3] + bias[2 * n8 + 1];
        }
    }
}

// ---------------- persistent HMMA LSTM layer, 64 CTAs -----------------------
// CTA owns units [8*bx, 8*bx+8) => 32 gate rows r = 4v+q (q = i,f,g,o).
// MMA: M=32, N=64(batch), K=512. Warp w: wm = w&1 (16 M-rows), wn = w>>1
// (16 batch cols). Per-CTA flag barrier (padded lines) for h exchange.
#define APAD   520                    // halfs per row (512 + 8 pad)
#define LA_OFF 0                      // A: 32 x APAD fp16 = 33280 B
#define LB_OFF 33280                  // B: 64 x APAD fp16 = 66560 B
#define LG_OFF 99840                  // Gs: 32 x 72 fp32 = 9216 B
#define LH_OFF 109056                 // hst: 64 x 8 fp16 = 1024 B
#define SM2_TOT 110080
#define GSTR   72

__global__ void __launch_bounds__(256) lstm_layer_mma2(
    const float* __restrict__ Whh,   // (2048, 512) fp32
    __half* __restrict__ h_all,      // (T, B, H) fp16: read t-1, write t
    const float* __restrict__ xg)    // (T, 4H, B) fp32 transposed x-gates
{
    extern __shared__ char sm[];
    const uint32_t sb = s2u(sm);
    const int tid  = threadIdx.x;
    const int w    = tid >> 5;
    const int lane = tid & 31;
    const int wm   = w & 1;
    const int wn   = w >> 1;
    const int u0   = blockIdx.x * 8;

    __half* Asm = (__half*)(sm + LA_OFF);
    __half* Bsm = (__half*)(sm + LB_OFF);
    float*  Gs  = (float*)(sm + LG_OFF);
    __half* hst = (__half*)(sm + LH_OFF);

    // ---- one-time: W slice fp32->fp16, rows r = 4v + q ----
#pragma unroll
    for (int i = 0; i < 8; i++) {
        int c = tid + i * 256;               // 0..2047 (8-half chunks)
        int r = c >> 6, ic = c & 63;         // row 0..31, chunk 0..63
        int g = (r & 3) * 512 + u0 + (r >> 2);
        float4 f0 = *(const float4*)(Whh + (size_t)g * HH + ic * 8);
        float4 f1 = *(const float4*)(Whh + (size_t)g * HH + ic * 8 + 4);
        __half2 h01 = __floats2half2_rn(f0.x, f0.y);
        __half2 h23 = __floats2half2_rn(f0.z, f0.w);
        __half2 h45 = __floats2half2_rn(f1.x, f1.y);
        __half2 h67 = __floats2half2_rn(f1.z, f1.w);
        uint4 hv;
        hv.x = *reinterpret_cast<uint32_t*>(&h01);
        hv.y = *reinterpret_cast<uint32_t*>(&h23);
        hv.z = *reinterpret_cast<uint32_t*>(&h45);
        hv.w = *reinterpret_cast<uint32_t*>(&h67);
        *(uint4*)(Asm + r * APAD + ic * 8) = hv;
    }
    __syncthreads();

    const uint32_t aAddr0 = sb + LA_OFF + (uint32_t)(16 * wm + (lane & 15)) * (APAD * 2)
                          + ((lane >> 4) & 1) * 16;
    const uint32_t bAddr0 = sb + LB_OFF + (uint32_t)(16 * wn + (lane & 15)) * (APAD * 2)
                          + ((lane >> 4) & 1) * 16;

    // pointwise ownership: unit v = tid>>5 (= warp id), batches pb, pb+1
    const int pv = tid >> 5;
    const int pb = 2 * (tid & 31);
    float2 creg = make_float2(0.f, 0.f);

    volatile unsigned* myflag = (volatile unsigned*)&g_arrive[blockIdx.x * 32];

    for (int t = 0; t < TT; t++) {
        // ---- prefetch this step's xg operands (h-independent) ----
        const float* xt = xg + (size_t)t * GG * 64;
        float2 xi = *(const float2*)(xt + (size_t)(u0 + pv)        * 64 + pb);
        float2 xf = *(const float2*)(xt + (size_t)(u0 + pv +  512) * 64 + pb);
        float2 xz = *(const float2*)(xt + (size_t)(u0 + pv + 1024) * 64 + pb);
        float2 xo = *(const float2*)(xt + (size_t)(u0 + pv + 1536) * 64 + pb);

        if (t > 0) {
            // wait for h(t-1): 64 pollers, one flag each
            if (tid < NC2) {
                volatile unsigned* f = (volatile unsigned*)&g_arrive[tid * 32];
                while (*f < (unsigned)t) __nanosleep(20);
            }
            __syncthreads();
            __threadfence();   // acquire

            const __half* hp = h_all + (size_t)(t - 1) * BB * HH;
#pragma unroll
            for (int i = 0; i < 16; i++) {
                int c = tid + i * 256;       // 0..4095 (8-half chunks)
                int b = c >> 6, ic = c & 63;
                uint4 v = *(const uint4*)(hp + (size_t)b * HH + ic * 8);
                *(uint4*)(Bsm + b * APAD + ic * 8) = v;
            }
            __syncthreads();
        }

        // ---- recurrent GEMM: warp (wm, wn) -> 16 rows x 16 batch ----
        float cfr[2][4];
#pragma unroll
        for (int nt = 0; nt < 2; nt++)
#pragma unroll
            for (int j = 0; j < 4; j++) cfr[nt][j] = 0.f;

        if (t > 0) {
#pragma unroll
            for (int kt = 0; kt < 32; kt++) {
                uint32_t a0, a1, a2, a3, b0, b1, b2, b3;
                ldsm_x4(aAddr0 + kt * 32, a0, a1, a2, a3);
                ldsm_x4(bAddr0 + kt * 32, b0, b1, b2, b3);
                mma16816(cfr[0], a0, a1, a2, a3, b0, b2);
                mma16816(cfr[1], a0, a1, a2, a3, b1, b3);
            }
        }

        // ---- stage gates into Gs[r][b] ----
        {
            int rA = 16 * wm + (lane >> 2);
            int cB = 16 * wn + 2 * (lane & 3);
            *(float2*)&Gs[rA * GSTR + cB]           = make_float2(cfr[0][0], cfr[0][1]);
            *(float2*)&Gs[(rA + 8) * GSTR + cB]     = make_float2(cfr[0][2], cfr[0][3]);
            *(float2*)&Gs[rA * GSTR + cB + 8]       = make_float2(cfr[1][0], cfr[1][1]);
            *(float2*)&Gs[(rA + 8) * GSTR + cB + 8] = make_float2(cfr[1][2], cfr[1][3]);
        }
        __syncthreads();

        // ---- pointwise: 2 (unit, batch) outputs per thread ----
        {
            float2 gi = *(const float2*)&Gs[(4 * pv + 0) * GSTR + pb];
            float2 gf = *(const float2*)&Gs[(4 * pv + 1) * GSTR + pb];
            float2 gz = *(const float2*)&Gs[(4 * pv + 2) * GSTR + pb];
            float2 go = *(const float2*)&Gs[(4 * pv + 3) * GSTR + pb];

            float cn0 = sigf(gf.x + xf.x) * creg.x + sigf(gi.x + xi.x) * tanf_(gz.x + xz.x);
            float cn1 = sigf(gf.y + xf.y) * creg.y + sigf(gi.y + xi.y) * tanf_(gz.y + xz.y);
            creg.x = cn0; creg.y = cn1;
            float hn0 = sigf(go.x + xo.x) * tanf_(cn0);
            float hn1 = sigf(go.y + xo.y) * tanf_(cn1);
            hst[(pb)     * 8 + pv] = __float2half(hn0);
            hst[(pb + 1) * 8 + pv] = __float2half(hn1);
        }
        __syncthreads();

        // ---- publish h(t): 64 x 16B stores + release flag ----
        if (tid < 64) {
            uint4 v = *(const uint4*)(hst + tid * 8);
            *(uint4*)(h_all + (size_t)t * BB * HH + (size_t)tid * HH + u0) = v;
        }
        __threadfence();
        __syncthreads();
        if (tid == 0) *myflag = (unsigned)(t + 1);
    }

    // ---- reset flags for next launch / graph replay ----
    __syncthreads();
    if (tid == 0) {
        unsigned d = atomicAdd(&g_done, 1u);
        if (d == (unsigned)(NC2 - 1)) {
            for (int j = 0; j < NC2; j++) g_arrive[j * 32] = 0u;
            __threadfence();
            g_done = 0u;
        }
    }
}

// ---------------- output projection + sigmoid (fp16 h) ----------------------
__global__ void __launch_bounds__(256) out_proj(
    const __half* __restrict__ h, const float* __restrict__ Wout,
    const float* __restrict__ bout, float* __restrict__ out)
{
    int row = blockIdx.x * 8 + (threadIdx.x >> 5);
    int l   = threadIdx.x & 31;
    const __half* hp = h + (size_t)row * HH;
    float s = 0.f;
#pragma unroll
    for (int i = 0; i < 2; i++) {
        uint4 hc = *(const uint4*)((const char*)hp + l * 32 + i * 16);
        const __half2* h2 = (const __half2*)&hc;
        float4 w0 = *(const float4*)(Wout + l * 16 + i * 8);
        float4 w1 = *(const float4*)(Wout + l * 16 + i * 8 + 4);
        s += __low2float(h2[0]) * w0.x + __high2float(h2[0]) * w0.y
           + __low2float(h2[1]) * w0.z + __high2float(h2[1]) * w0.w
           + __low2float(h2[2]) * w1.x + __high2float(h2[2]) * w1.y
           + __low2float(h2[3]) * w1.z + __high2float(h2[3]) * w1.w;
    }
#pragma unroll
    for (int o = 16; o > 0; o >>= 1) s += __shfl_xor_sync(0xffffffffu, s, o);
    if (l == 0) out[row] = 1.f / (1.f + expf(-(s + bout[0])));
}

// ---------------- launch -----------------------------------------------------
extern "C" void kernel_launch(void* const* d_in, const int* in_sizes, int n_in,
                              void* d_out, int out_size)
{
    const float* input = (const float*)d_in[0];
    const float* W_ih1 = (const float*)d_in[1];
    const float* W_hh1 = (const float*)d_in[2];
    const float* b_ih1 = (const float*)d_in[3];
    const float* b_hh1 = (const float*)d_in[4];
    const float* W_ih2 = (const float*)d_in[5];
    const float* W_hh2 = (const float*)d_in[6];
    const float* b_ih2 = (const float*)d_in[7];
    const float* b_hh2 = (const float*)d_in[8];
    const float* W_out = (const float*)d_in[9];
    const float* b_out = (const float*)d_in[10];
    float* out = (float*)d_out;

    float*  xg;
    __half* h;
    __half* x16;
    __half* w16;
    cudaGetSymbolAddress((void**)&xg,  g_xg);
    cudaGetSymbolAddress((void**)&h,   g_h);
    cudaGetSymbolAddress((void**)&x16, g_x16);
    cudaGetSymbolAddress((void**)&w16, g_w16);

    cudaFuncSetAttribute(lstm_layer_mma2, cudaFuncAttributeMaxDynamicSharedMemorySize,
                         SM2_TOT);
    cudaFuncSetAttribute(hgemm_xg<IN1>, cudaFuncAttributeMaxDynamicSharedMemorySize,
                         HG_SMEM);
    cudaFuncSetAttribute(hgemm_xg<HH>,  cudaFuncAttributeMaxDynamicSharedMemorySize,
                         HG_SMEM);

    dim3 hg(GG / 128, (TT * BB) / 128);   // (16, 1024)

    // Layer 1
    f32to16<<<(TT * BB * IN1) / 2048, 256>>>(input, x16);
    f32to16<<<(GG * IN1) / 2048, 256>>>(W_ih1, w16);
    hgemm_xg<IN1><<<hg, 256, HG_SMEM>>>(x16, w16, b_ih1, b_hh1, xg);
    lstm_layer_mma2<<<NC2, 256, SM2_TOT>>>(W_hh1, h, xg);

    // Layer 2
    f32to16<<<(GG * HH) / 2048, 256>>>(W_ih2, w16);
    hgemm_xg<HH><<<hg, 256, HG_SMEM>>>(h, w16, b_ih2, b_hh2, xg);
    lstm_layer_mma2<<<NC2, 256, SM2_TOT>>>(W_hh2, h, xg);

    out_proj<<<(TT * BB) / 8, 256>>>(h, W_out, b_out, out);
}

// round 8
// speedup vs baseline: 2.7256x; 1.1530x over previous
#include <cuda_runtime.h>
#include <cuda_fp16.h>
#include <math.h>
#include <stdint.h>

#define TT 2048
#define BB 64
#define IN1 256
#define HH 512
#define GG 2048   // 4*HH
#define NC2 64    // CTAs per layer (each owns 8 hidden units)

// ---------------- scratch (static device globals; allocation-free) ----------
__device__ float  g_xg [(size_t)TT * GG * BB];   // 1 GB: xg1 transposed [t][g][b]
__device__ __half g_h1 [(size_t)TT * BB * HH];   // 128 MB: layer-1 h history
__device__ __half g_h2 [(size_t)TT * BB * HH];   // 128 MB: layer-2 h history
__device__ __half g_x16[(size_t)TT * BB * IN1];  // 64 MB: fp16 input
__device__ __half g_w16[(size_t)GG * HH];        // 2 MB: fp16 W_ih1
__device__ unsigned g_arr1[NC2 * 32];            // layer-1 per-CTA step flags
__device__ unsigned g_arr2[NC2 * 32];            // layer-2 per-CTA step flags
__device__ unsigned g_done;                      // end-of-kernel reset counter

// ======================= helpers ============================================
__device__ __forceinline__ uint32_t s2u(const void* p) {
    uint32_t a;
    asm("{ .reg .u64 t; cvta.to.shared.u64 t, %1; cvt.u32.u64 %0, t; }"
        : "=r"(a) : "l"(p));
    return a;
}
__device__ __forceinline__ void ldsm_x4(uint32_t a, uint32_t& r0, uint32_t& r1,
                                        uint32_t& r2, uint32_t& r3) {
    asm volatile("ldmatrix.sync.aligned.m8n8.x4.shared.b16 {%0,%1,%2,%3}, [%4];"
                 : "=r"(r0), "=r"(r1), "=r"(r2), "=r"(r3) : "r"(a));
}
__device__ __forceinline__ void mma16816(float* c, uint32_t a0, uint32_t a1,
                                         uint32_t a2, uint32_t a3,
                                         uint32_t b0, uint32_t b1) {
    asm volatile(
        "mma.sync.aligned.m16n8k16.row.col.f32.f16.f16.f32 "
        "{%0,%1,%2,%3}, {%4,%5,%6,%7}, {%8,%9}, {%0,%1,%2,%3};"
        : "+f"(c[0]), "+f"(c[1]), "+f"(c[2]), "+f"(c[3])
        : "r"(a0), "r"(a1), "r"(a2), "r"(a3), "r"(b0), "r"(b1));
}
__device__ __forceinline__ void cp16(uint32_t saddr, const void* g) {
    asm volatile("cp.async.cg.shared.global [%0], [%1], 16;"
                 :: "r"(saddr), "l"(g));
}
#define CP_COMMIT() asm volatile("cp.async.commit_group;" ::: "memory")
#define CP_WAIT1()  asm volatile("cp.async.wait_group 1;" ::: "memory")
__device__ __forceinline__ float sigf(float x) {
    return __fdividef(1.f, 1.f + __expf(-x));
}
__device__ __forceinline__ float tanf_(float x) {
    return 1.f - __fdividef(2.f, __expf(2.f * x) + 1.f);
}

// ---------------- fp32 -> fp16 conversion ----------------------------------
__global__ void __launch_bounds__(256) f32to16(const float* __restrict__ src,
                                               __half* __restrict__ dst) {
    size_t i = ((size_t)blockIdx.x * 256 + threadIdx.x) * 8;
    float4 a = *(const float4*)(src + i);
    float4 b = *(const float4*)(src + i + 4);
    __half2 h0 = __floats2half2_rn(a.x, a.y);
    __half2 h1 = __floats2half2_rn(a.z, a.w);
    __half2 h2 = __floats2half2_rn(b.x, b.y);
    __half2 h3 = __floats2half2_rn(b.z, b.w);
    uint4 v;
    v.x = *reinterpret_cast<uint32_t*>(&h0);
    v.y = *reinterpret_cast<uint32_t*>(&h1);
    v.z = *reinterpret_cast<uint32_t*>(&h2);
    v.w = *reinterpret_cast<uint32_t*>(&h3);
    *(uint4*)(dst + i) = v;
}

// ---------------- HMMA GEMM for layer-1 xg (K=256) --------------------------
#define KC    64
#define RS    144
#define STG   (128 * RS)
#define HG_SMEM (4 * STG)

template <int K>
__global__ void __launch_bounds__(256) hgemm_xg(
    const __half* __restrict__ A, const __half* __restrict__ W,
    const float* __restrict__ b1, const float* __restrict__ b2,
    float* __restrict__ C)
{
    extern __shared__ char sm[];
    const uint32_t sbA = s2u(sm);
    const uint32_t sbB = sbA + 2 * STG;
    const int tid  = threadIdx.x;
    const int w    = tid >> 5;
    const int lane = tid & 31;
    const int wm   = w & 1;
    const int wn   = w >> 1;
    const int bm   = blockIdx.y * 128;
    const int bn   = blockIdx.x * 128;

    float cacc[4][4][4];
#pragma unroll
    for (int mt = 0; mt < 4; mt++)
#pragma unroll
        for (int n8 = 0; n8 < 4; n8++)
#pragma unroll
            for (int j = 0; j < 4; j++) cacc[mt][n8][j] = 0.f;

    float bias[8];
#pragma unroll
    for (int n8 = 0; n8 < 4; n8++) {
        int g = bn + wn * 32 + n8 * 8 + 2 * (lane & 3);
        bias[2 * n8]     = b1[g] + b2[g];
        bias[2 * n8 + 1] = b1[g + 1] + b2[g + 1];
    }

    const int nK = K / KC;

    auto load_stage = [&](int kc, int s) {
#pragma unroll
        for (int p = 0; p < 4; p++) {
            int idx = tid + p * 256;
            int row = idx >> 3;
            int c8  = idx & 7;
            cp16(sbA + s * STG + row * RS + c8 * 16,
                 A + (size_t)(bm + row) * K + kc * KC + c8 * 8);
            cp16(sbB + s * STG + row * RS + c8 * 16,
                 W + (size_t)(bn + row) * K + kc * KC + c8 * 8);
        }
    };

    load_stage(0, 0);
    CP_COMMIT();

    const uint32_t aBase0 = sbA + (uint32_t)(wm * 64 + (lane & 15)) * RS
                          + (lane >> 4) * 16;
    const uint32_t bBase0 = sbB + (uint32_t)(wn * 32 + (lane & 15)) * RS
                          + (lane >> 4) * 16;

    for (int kc = 0; kc < nK; kc++) {
        int s = kc & 1;
        if (kc + 1 < nK) load_stage(kc + 1, s ^ 1);
        CP_COMMIT();
        CP_WAIT1();
        __syncthreads();

        const uint32_t aB = aBase0 + s * STG;
        const uint32_t bB = bBase0 + s * STG;
#pragma unroll
        for (int kt = 0; kt < 4; kt++) {
            uint32_t a[4][4];
#pragma unroll
            for (int mt = 0; mt < 4; mt++)
                ldsm_x4(aB + mt * 16 * RS + kt * 32,
                        a[mt][0], a[mt][1], a[mt][2], a[mt][3]);
#pragma unroll
            for (int nt = 0; nt < 2; nt++) {
                uint32_t r0, r1, r2, r3;
                ldsm_x4(bB + nt * 16 * RS + kt * 32, r0, r1, r2, r3);
#pragma unroll
                for (int mt = 0; mt < 4; mt++) {
                    mma16816(cacc[mt][nt * 2],     a[mt][0], a[mt][1], a[mt][2], a[mt][3], r0, r2);
                    mma16816(cacc[mt][nt * 2 + 1], a[mt][0], a[mt][1], a[mt][2], a[mt][3], r1, r3);
                }
            }
        }
        __syncthreads();
    }

#pragma unroll
    for (int mt = 0; mt < 4; mt++) {
        int m0 = bm + wm * 64 + mt * 16 + (lane >> 2);
        int m1 = m0 + 8;
        size_t base0 = (size_t)(m0 >> 6) * GG * 64 + (m0 & 63);
        size_t base1 = (size_t)(m1 >> 6) * GG * 64 + (m1 & 63);
#pragma unroll
        for (int n8 = 0; n8 < 4; n8++) {
            int g = bn + wn * 32 + n8 * 8 + 2 * (lane & 3);
            const float* cf = cacc[mt][n8];
            C[base0 + (size_t)g * 64]       = cf[0] + bias[2 * n8];
            C[base0 + (size_t)(g + 1) * 64] = cf[1] + bias[2 * n8 + 1];
            C[base1 + (size_t)g * 64]       = cf[2] + bias[2 * n8];
            C[base1 + (size_t)(g + 1) * 64] = cf[3] + bias[2 * n8 + 1];
        }
    }
}

// ---------------- fused persistent LSTM: both layers, 128 CTAs --------------
// CTAs 0..63  = layer 1 (units 8*bx..+8): gates1 = W_hh1·h1(t-1) + xg1[t]
// CTAs 64..127 = layer 2 (units 8*cx..+8): gates2 = W_ih2·h1(t) + W_hh2·h2(t-1) + b
//   layer-2 A-tile = [W_ih2 slice | W_hh2 slice] (32 x 1024 fp16)
//   layer-2 B-tile = [h1(t) | h2(t-1)]           (64 x 1024 fp16)
// Rows r = 4v + q (q = i,f,g,o). Warp w: wm=w&1 (16 rows), wn=w>>1 (16 batch).
#define AP2    1032                   // halfs per SMEM row (1024 + 8 pad)
#define LA_OFF 0                      // A: 32 x AP2 fp16 = 66048 B
#define LB_OFF 66048                  // B: 64 x AP2 fp16 = 132096 B
#define LG_OFF 198144                 // Gs: 32 x 72 fp32 = 9216 B
#define LH_OFF 207360                 // hst: 64 x 8 fp16 = 1024 B
#define SMF_TOT 208384
#define GSTR   72

__global__ void __launch_bounds__(256) lstm_fused(
    const float* __restrict__ Whh1,
    const float* __restrict__ Wih2, const float* __restrict__ Whh2,
    const float* __restrict__ bih2, const float* __restrict__ bhh2,
    const float* __restrict__ xg,    // (T, 4H, B) layer-1 x-gates
    __half* __restrict__ h1, __half* __restrict__ h2)
{
    extern __shared__ char sm[];
    const uint32_t sb = s2u(sm);
    const int tid  = threadIdx.x;
    const int w    = tid >> 5;
    const int lane = tid & 31;
    const int wm   = w & 1;
    const int wn   = w >> 1;
    const bool L2  = blockIdx.x >= NC2;
    const int cx   = L2 ? blockIdx.x - NC2 : blockIdx.x;
    const int u0   = cx * 8;

    __half* Asm = (__half*)(sm + LA_OFF);
    __half* Bsm = (__half*)(sm + LB_OFF);
    float*  Gs  = (float*)(sm + LG_OFF);
    __half* hst = (__half*)(sm + LH_OFF);

    // ---- one-time A fill: W fp32->fp16, rows r = 4v + q ----
    auto fillA = [&](const float* W, int colbase) {
#pragma unroll
        for (int i = 0; i < 8; i++) {
            int c = tid + i * 256;           // 0..2047 (8-half chunks)
            int r = c >> 6, ic = c & 63;
            int g = (r & 3) * 512 + u0 + (r >> 2);
            float4 f0 = *(const float4*)(W + (size_t)g * HH + ic * 8);
            float4 f1 = *(const float4*)(W + (size_t)g * HH + ic * 8 + 4);
            __half2 p0 = __floats2half2_rn(f0.x, f0.y);
            __half2 p1 = __floats2half2_rn(f0.z, f0.w);
            __half2 p2 = __floats2half2_rn(f1.x, f1.y);
            __half2 p3 = __floats2half2_rn(f1.z, f1.w);
            uint4 hv;
            hv.x = *reinterpret_cast<uint32_t*>(&p0);
            hv.y = *reinterpret_cast<uint32_t*>(&p1);
            hv.z = *reinterpret_cast<uint32_t*>(&p2);
            hv.w = *reinterpret_cast<uint32_t*>(&p3);
            *(uint4*)(Asm + r * AP2 + colbase + ic * 8) = hv;
        }
    };
    if (L2) { fillA(Wih2, 0); fillA(Whh2, 512); }
    else    { fillA(Whh1, 0); }

    if (L2) {
        // zero B cols 512..1023 (h2(-1) = 0 for t = 0)
#pragma unroll
        for (int i = 0; i < 16; i++) {
            int c = tid + i * 256;
            int b = c >> 6, ic = c & 63;
            *(uint4*)(Bsm + b * AP2 + 512 + ic * 8) = make_uint4(0, 0, 0, 0);
        }
    }
    __syncthreads();

    const uint32_t aAddr0 = sb + LA_OFF + (uint32_t)(16 * wm + (lane & 15)) * (AP2 * 2)
                          + ((lane >> 4) & 1) * 16;
    const uint32_t bAddr0 = sb + LB_OFF + (uint32_t)(16 * wn + (lane & 15)) * (AP2 * 2)
                          + ((lane >> 4) & 1) * 16;

    // pointwise ownership: unit v = warp id, batches pb, pb+1
    const int pv = tid >> 5;
    const int pb = 2 * (tid & 31);
    float2 creg = make_float2(0.f, 0.f);

    // layer-2 bias constants (xg replaced by in-MMA projection + bias)
    float2 xi, xf, xz, xo;
    if (L2) {
        float bi = bih2[u0 + pv]        + bhh2[u0 + pv];
        float bf = bih2[u0 + pv + 512]  + bhh2[u0 + pv + 512];
        float bz = bih2[u0 + pv + 1024] + bhh2[u0 + pv + 1024];
        float bo = bih2[u0 + pv + 1536] + bhh2[u0 + pv + 1536];
        xi = make_float2(bi, bi); xf = make_float2(bf, bf);
        xz = make_float2(bz, bz); xo = make_float2(bo, bo);
    }

    volatile unsigned* myflag = L2 ? (volatile unsigned*)&g_arr2[cx * 32]
                                   : (volatile unsigned*)&g_arr1[cx * 32];
    __half* hout = L2 ? h2 : h1;

    for (int t = 0; t < TT; t++) {
        if (!L2) {
            // prefetch xg1 operands (h-independent)
            const float* xt = xg + (size_t)t * GG * 64;
            xi = *(const float2*)(xt + (size_t)(u0 + pv)        * 64 + pb);
            xf = *(const float2*)(xt + (size_t)(u0 + pv +  512) * 64 + pb);
            xz = *(const float2*)(xt + (size_t)(u0 + pv + 1024) * 64 + pb);
            xo = *(const float2*)(xt + (size_t)(u0 + pv + 1536) * 64 + pb);

            if (t > 0) {
                if (tid < NC2) {
                    volatile unsigned* f = (volatile unsigned*)&g_arr1[tid * 32];
                    while (*f < (unsigned)t) __nanosleep(20);
                }
                __syncthreads();
                __threadfence();   // acquire

                const __half* hp = h1 + (size_t)(t - 1) * BB * HH;
#pragma unroll
                for (int i = 0; i < 16; i++) {
                    int c = tid + i * 256;
                    int b = c >> 6, ic = c & 63;
                    uint4 v = *(const uint4*)(hp + (size_t)b * HH + ic * 8);
                    *(uint4*)(Bsm + b * AP2 + ic * 8) = v;
                }
                __syncthreads();
            }
        } else {
            // wait: h1(t) from layer 1, h2(t-1) from own layer
            if (tid < NC2) {
                volatile unsigned* f = (volatile unsigned*)&g_arr1[tid * 32];
                while (*f < (unsigned)(t + 1)) __nanosleep(20);
            } else if (tid < 2 * NC2 && t > 0) {
                volatile unsigned* f = (volatile unsigned*)&g_arr2[(tid - NC2) * 32];
                while (*f < (unsigned)t) __nanosleep(20);
            }
            __syncthreads();
            __threadfence();   // acquire

            const __half* hp1 = h1 + (size_t)t * BB * HH;
#pragma unroll
            for (int i = 0; i < 16; i++) {
                int c = tid + i * 256;
                int b = c >> 6, ic = c & 63;
                uint4 v = *(const uint4*)(hp1 + (size_t)b * HH + ic * 8);
                *(uint4*)(Bsm + b * AP2 + ic * 8) = v;
            }
            if (t > 0) {
                const __half* hp2 = h2 + (size_t)(t - 1) * BB * HH;
#pragma unroll
                for (int i = 0; i < 16; i++) {
                    int c = tid + i * 256;
                    int b = c >> 6, ic = c & 63;
                    uint4 v = *(const uint4*)(hp2 + (size_t)b * HH + ic * 8);
                    *(uint4*)(Bsm + b * AP2 + 512 + ic * 8) = v;
                }
            }
            __syncthreads();
        }

        // ---- recurrent GEMM ----
        float cfr[2][4];
#pragma unroll
        for (int nt = 0; nt < 2; nt++)
#pragma unroll
            for (int j = 0; j < 4; j++) cfr[nt][j] = 0.f;

        if (L2) {
#pragma unroll 16
            for (int kt = 0; kt < 64; kt++) {
                uint32_t a0, a1, a2, a3, b0, b1, b2, b3;
                ldsm_x4(aAddr0 + kt * 32, a0, a1, a2, a3);
                ldsm_x4(bAddr0 + kt * 32, b0, b1, b2, b3);
                mma16816(cfr[0], a0, a1, a2, a3, b0, b2);
                mma16816(cfr[1], a0, a1, a2, a3, b1, b3);
            }
        } else if (t > 0) {
#pragma unroll 16
            for (int kt = 0; kt < 32; kt++) {
                uint32_t a0, a1, a2, a3, b0, b1, b2, b3;
                ldsm_x4(aAddr0 + kt * 32, a0, a1, a2, a3);
                ldsm_x4(bAddr0 + kt * 32, b0, b1, b2, b3);
                mma16816(cfr[0], a0, a1, a2, a3, b0, b2);
                mma16816(cfr[1], a0, a1, a2, a3, b1, b3);
            }
        }

        // ---- stage gates into Gs[r][b] ----
        {
            int rA = 16 * wm + (lane >> 2);
            int cB = 16 * wn + 2 * (lane & 3);
            *(float2*)&Gs[rA * GSTR + cB]           = make_float2(cfr[0][0], cfr[0][1]);
            *(float2*)&Gs[(rA + 8) * GSTR + cB]     = make_float2(cfr[0][2], cfr[0][3]);
            *(float2*)&Gs[rA * GSTR + cB + 8]       = make_float2(cfr[1][0], cfr[1][1]);
            *(float2*)&Gs[(rA + 8) * GSTR + cB + 8] = make_float2(cfr[1][2], cfr[1][3]);
        }
        __syncthreads();

        // ---- pointwise ----
        {
            float2 gi = *(const float2*)&Gs[(4 * pv + 0) * GSTR + pb];
            float2 gf = *(const float2*)&Gs[(4 * pv + 1) * GSTR + pb];
            float2 gz = *(const float2*)&Gs[(4 * pv + 2) * GSTR + pb];
            float2 go = *(const float2*)&Gs[(4 * pv + 3) * GSTR + pb];

            float cn0 = sigf(gf.x + xf.x) * creg.x + sigf(gi.x + xi.x) * tanf_(gz.x + xz.x);
            float cn1 = sigf(gf.y + xf.y) * creg.y + sigf(gi.y + xi.y) * tanf_(gz.y + xz.y);
            creg.x = cn0; creg.y = cn1;
            float hn0 = sigf(go.x + xo.x) * tanf_(cn0);
            float hn1 = sigf(go.y + xo.y) * tanf_(cn1);
            hst[(pb)     * 8 + pv] = __float2half(hn0);
            hst[(pb + 1) * 8 + pv] = __float2half(hn1);
        }
        __syncthreads();

        // ---- publish h(t) ----
        if (tid < 64) {
            uint4 v = *(const uint4*)(hst + tid * 8);
            *(uint4*)(hout + (size_t)t * BB * HH + (size_t)tid * HH + u0) = v;
        }
        __threadfence();
        __syncthreads();
        if (tid == 0) *myflag = (unsigned)(t + 1);
    }

    // ---- reset flags for next launch / graph replay ----
    __syncthreads();
    if (tid == 0) {
        unsigned d = atomicAdd(&g_done, 1u);
        if (d == (unsigned)(2 * NC2 - 1)) {
            for (int j = 0; j < NC2; j++) { g_arr1[j * 32] = 0u; g_arr2[j * 32] = 0u; }
            __threadfence();
            g_done = 0u;
        }
    }
}

// ---------------- output projection + sigmoid (fp16 h) ----------------------
__global__ void __launch_bounds__(256) out_proj(
    const __half* __restrict__ h, const float* __restrict__ Wout,
    const float* __restrict__ bout, float* __restrict__ out)
{
    int row = blockIdx.x * 8 + (threadIdx.x >> 5);
    int l   = threadIdx.x & 31;
    const __half* hp = h + (size_t)row * HH;
    float s = 0.f;
#pragma unroll
    for (int i = 0; i < 2; i++) {
        uint4 hc = *(const uint4*)((const char*)hp + l * 32 + i * 16);
        const __half2* h2 = (const __half2*)&hc;
        float4 w0 = *(const float4*)(Wout + l * 16 + i * 8);
        float4 w1 = *(const float4*)(Wout + l * 16 + i * 8 + 4);
        s += __low2float(h2[0]) * w0.x + __high2float(h2[0]) * w0.y
           + __low2float(h2[1]) * w0.z + __high2float(h2[1]) * w0.w
           + __low2float(h2[2]) * w1.x + __high2float(h2[2]) * w1.y
           + __low2float(h2[3]) * w1.z + __high2float(h2[3]) * w1.w;
    }
#pragma unroll
    for (int o = 16; o > 0; o >>= 1) s += __shfl_xor_sync(0xffffffffu, s, o);
    if (l == 0) out[row] = 1.f / (1.f + expf(-(s + bout[0])));
}

// ---------------- launch -----------------------------------------------------
extern "C" void kernel_launch(void* const* d_in, const int* in_sizes, int n_in,
                              void* d_out, int out_size)
{
    const float* input = (const float*)d_in[0];
    const float* W_ih1 = (const float*)d_in[1];
    const float* W_hh1 = (const float*)d_in[2];
    const float* b_ih1 = (const float*)d_in[3];
    const float* b_hh1 = (const float*)d_in[4];
    const float* W_ih2 = (const float*)d_in[5];
    const float* W_hh2 = (const float*)d_in[6];
    const float* b_ih2 = (const float*)d_in[7];
    const float* b_hh2 = (const float*)d_in[8];
    const float* W_out = (const float*)d_in[9];
    const float* b_out = (const float*)d_in[10];
    float* out = (float*)d_out;

    float*  xg;
    __half *h1, *h2, *x16, *w16;
    cudaGetSymbolAddress((void**)&xg,  g_xg);
    cudaGetSymbolAddress((void**)&h1,  g_h1);
    cudaGetSymbolAddress((void**)&h2,  g_h2);
    cudaGetSymbolAddress((void**)&x16, g_x16);
    cudaGetSymbolAddress((void**)&w16, g_w16);

    cudaFuncSetAttribute(lstm_fused, cudaFuncAttributeMaxDynamicSharedMemorySize,
                         SMF_TOT);
    cudaFuncSetAttribute(hgemm_xg<IN1>, cudaFuncAttributeMaxDynamicSharedMemorySize,
                         HG_SMEM);

    dim3 hg(GG / 128, (TT * BB) / 128);   // (16, 1024)

    // layer-1 x-projection (tensor cores), then both recurrences fused/pipelined
    f32to16<<<(TT * BB * IN1) / 2048, 256>>>(input, x16);
    f32to16<<<(GG * IN1) / 2048, 256>>>(W_ih1, w16);
    hgemm_xg<IN1><<<hg, 256, HG_SMEM>>>(x16, w16, b_ih1, b_hh1, xg);
    lstm_fused<<<2 * NC2, 256, SMF_TOT>>>(W_hh1, W_ih2, W_hh2, b_ih2, b_hh2,
                                          xg, h1, h2);

    out_proj<<<(TT * BB) / 8, 256>>>(h2, W_out, b_out, out);
}